// round 15
// baseline (speedup 1.0000x reference)
#include <cuda_runtime.h>
#include <cuda_fp16.h>
#include <cstdint>
#include <math.h>

#define B_ 64
#define S_ 2048
#define H_ 512
#define F_ 128

// ---------------- persistent device scratch (no allocations allowed) -------
__device__ __align__(16) __half g_WencHi[H_ * H_];   // [n][k], k contiguous
__device__ __align__(16) __half g_WencLo[H_ * H_];
__device__ __align__(16) __half g_WzHi[H_ * F_];     // [n][k]
__device__ __align__(16) __half g_WzLo[H_ * F_];
__device__ __align__(16) __half g_ctx16[B_ * S_ * H_];   // fp16 copy of context
__device__ __align__(16) __half g_z16[B_ * S_ * F_];     // fp16 copy of input_z
__device__ float g_proj_a[B_ * H_];
__device__ float g_proj_b[B_ * H_];
__device__ float g_scores[B_ * S_];
__device__ float g_wcpart[8 * B_ * H_];       // weighted-context partials

// ---------------- helpers --------------------------------------------------
static __device__ __forceinline__ uint32_t smem_u32(const void* p) {
    uint32_t a;
    asm("{ .reg .u64 t; cvta.to.shared.u64 t, %1; cvt.u32.u64 %0, t; }"
        : "=r"(a) : "l"(p));
    return a;
}

static __device__ __forceinline__ void mma_f16(float d[4], const unsigned a[4],
                                               const unsigned b[2]) {
    asm volatile(
        "mma.sync.aligned.m16n8k16.row.col.f32.f16.f16.f32 "
        "{%0,%1,%2,%3}, {%4,%5,%6,%7}, {%8,%9}, {%0,%1,%2,%3};\n"
        : "+f"(d[0]), "+f"(d[1]), "+f"(d[2]), "+f"(d[3])
        : "r"(a[0]), "r"(a[1]), "r"(a[2]), "r"(a[3]), "r"(b[0]), "r"(b[1]));
}

static __device__ __forceinline__ void ldsm4(unsigned r[4], uint32_t addr) {
    asm volatile("ldmatrix.sync.aligned.m8n8.x4.shared.b16 {%0,%1,%2,%3}, [%4];"
                 : "=r"(r[0]), "=r"(r[1]), "=r"(r[2]), "=r"(r[3]) : "r"(addr));
}

static __device__ __forceinline__ void cp16(uint32_t dst, const void* src) {
    asm volatile("cp.async.cg.shared.global [%0], [%1], 16;\n" ::"r"(dst), "l"(src));
}
static __device__ __forceinline__ void cp_commit() {
    asm volatile("cp.async.commit_group;\n" ::: "memory");
}
static __device__ __forceinline__ void cp_wait0() {
    asm volatile("cp.async.wait_group 0;\n" ::: "memory");
}

static __device__ __forceinline__ void split_f16(float x, __half& hi, __half& lo) {
    hi = __float2half_rn(x);
    lo = __float2half_rn(x - __half2float(hi));
}

// ---------------- kernel 0: fp32 -> fp16 bulk convert -----------------------
// which: 0 -> g_ctx16, 1 -> g_z16. Each thread converts 8 floats.
__global__ void conv16_kernel(const float* __restrict__ src, int which) {
    size_t i8 = (size_t)blockIdx.x * 256 + threadIdx.x;
    size_t base = i8 * 8;
    float4 v0 = *(const float4*)(src + base);
    float4 v1 = *(const float4*)(src + base + 4);
    __half2 h0 = __floats2half2_rn(v0.x, v0.y);
    __half2 h1 = __floats2half2_rn(v0.z, v0.w);
    __half2 h2 = __floats2half2_rn(v1.x, v1.y);
    __half2 h3 = __floats2half2_rn(v1.z, v1.w);
    uint4 out = make_uint4(*(uint32_t*)&h0, *(uint32_t*)&h1,
                           *(uint32_t*)&h2, *(uint32_t*)&h3);
    __half* dst = which ? g_z16 : g_ctx16;
    *(uint4*)(dst + base) = out;
}

// ---------------- kernel 1: split + transpose weights ----------------------
__global__ void prep_kernel(const float* __restrict__ Wenc,
                            const float* __restrict__ Wz) {
    int idx = blockIdx.x * 256 + threadIdx.x;      // 1024*256 = 262144 = 512*512
    {
        float w = Wenc[idx];                       // [k][n] row-major
        __half hi, lo;
        split_f16(w, hi, lo);
        int k = idx >> 9, n = idx & 511;
        g_WencHi[n * H_ + k] = hi;
        g_WencLo[n * H_ + k] = lo;
    }
    if (idx < F_ * H_) {                           // Wz [f][n]
        float w = Wz[idx];
        __half hi, lo;
        split_f16(w, hi, lo);
        int f = idx >> 9, n = idx & 511;
        g_WzHi[n * F_ + f] = hi;
        g_WzLo[n * F_ + f] = lo;
    }
}

// ---------------- kernel 2: proj_in_a / proj_in_b --------------------------
__global__ void proj_in_kernel(const float* __restrict__ input,
                               const float* __restrict__ W_a,
                               const float* __restrict__ b_a,
                               const float* __restrict__ W_b,
                               const float* __restrict__ b_b) {
    __shared__ float x[H_];
    int b = blockIdx.x, tid = threadIdx.x;         // 256 threads
    x[tid] = input[b * H_ + tid];
    x[tid + 256] = input[b * H_ + tid + 256];
    __syncthreads();
    for (int h = tid; h < H_; h += 256) {
        float aa = 0.f, ab = 0.f;
#pragma unroll 8
        for (int j = 0; j < H_; ++j) {
            float xv = x[j];
            aa += xv * W_a[j * H_ + h];
            ab += xv * W_b[j * H_ + h];
        }
        g_proj_a[b * H_ + h] = tanhf(aa + b_a[h]);
        g_proj_b[b * H_ + h] = tanhf(ab + b_b[h]);
    }
}

// ---------------- kernels 3/4: fused score via mma.sync + ldmatrix ---------
// Per block: 64 rows x full H, n-passes of 128 cols, K streamed in 64-chunks.
// ALL operands arrive via cp.async from pre-converted fp16 globals.
// Precision: A single fp16, B split fp16 (hi+lo) -> C = A*(Bh+Bl), fp32 acc.
// Stage layout: A[64x64]=8K | Bhi[128x64]=16K | Blo=16K   (SW128 swizzle)
template <int KTOT, int ADD>
__global__ void __launch_bounds__(256, 2)
score_mma_kernel(const float* __restrict__ bias) { // [H]
    constexpr int NCHUNK = KTOT / 64;
    constexpr uint32_t STAGE = 40960u;
    constexpr uint32_t BH_OFF = 8192u;
    constexpr uint32_t BL_OFF = 24576u;
    extern __shared__ char smem_raw[];
    __shared__ float ssc[64];
    const uint32_t sb = smem_u32(smem_raw);

    const int tid = threadIdx.x;
    const int lane = tid & 31, wid = tid >> 5;
    const int wm = wid & 1, wn = wid >> 1;        // 2 M-warps x 4 N-warps
    const int g = lane >> 2, q = lane & 3;

    const int b = blockIdx.x >> 5;                // 32 row-tiles per batch
    const int s0 = (blockIdx.x & 31) << 6;

    const __half* __restrict__ A16 = (KTOT == H_) ? g_ctx16 : g_z16;
    const __half* __restrict__ Whi = (KTOT == H_) ? g_WencHi : g_WzHi;
    const __half* __restrict__ Wlo = (KTOT == H_) ? g_WencLo : g_WzLo;
    const float* __restrict__ avec =
        ((KTOT == H_) ? g_proj_a : g_proj_b) + b * H_;

    if (tid < 64) ssc[tid] = 0.f;

    // A loader mapping: 4 threads/row, 2x 16B segments each
    const int ar = tid >> 2, aseg = (tid & 3) << 1;
    const __half* aG = A16 + (size_t)(b * S_ + s0 + ar) * KTOT + aseg * 8;
    const uint32_t swa = (uint32_t)((ar & 7) << 4);
    const uint32_t aOff0 = (uint32_t)(ar * 128) + (((uint32_t)(aseg * 16)) ^ swa);
    const uint32_t aOff1 =
        (uint32_t)(ar * 128) + (((uint32_t)((aseg + 1) * 16)) ^ swa);
    // B loader mapping: 2 threads/row, 4x 16B segments each (hi and lo)
    const int bn = tid >> 1, bseg0 = (tid & 1) * 4;
    const uint32_t swb = (uint32_t)((bn & 7) << 4);
    const uint32_t bRow = (uint32_t)(bn * 128);

    // ldmatrix per-lane constants
    const uint32_t swl = (uint32_t)((lane & 7) << 4);
    const uint32_t rowA0 = (uint32_t)((wm * 32 + (lane & 15)) * 128);
    const uint32_t rowA1 = rowA0 + 16 * 128;
    const uint32_t klA = (uint32_t)((lane >> 4) << 4);
    const uint32_t rowB0 =
        (uint32_t)((wn * 32 + (lane & 7) + ((lane >> 4) << 3)) * 128);
    const uint32_t rowB1 = rowB0 + 16 * 128;
    const uint32_t klB = (uint32_t)(((lane >> 3) & 1) << 4);

    float sc[4] = {0.f, 0.f, 0.f, 0.f};

    for (int p = 0; p < 4; ++p) {
        const int n0 = p * 128;
        float acc[2][4][4];
#pragma unroll
        for (int mf = 0; mf < 2; ++mf)
#pragma unroll
            for (int nf = 0; nf < 4; ++nf)
#pragma unroll
                for (int e = 0; e < 4; ++e) acc[mf][nf][e] = 0.f;

        // ---- prologue: chunk 0 -> stage 0
        {
            cp16(sb + aOff0, aG);
            cp16(sb + aOff1, aG + 8);
            const __half* shh = Whi + (size_t)(n0 + bn) * KTOT + bseg0 * 8;
            const __half* sll = Wlo + (size_t)(n0 + bn) * KTOT + bseg0 * 8;
#pragma unroll
            for (int j = 0; j < 4; ++j) {
                uint32_t off = bRow + (((uint32_t)((bseg0 + j) * 16)) ^ swb);
                cp16(sb + BH_OFF + off, shh + j * 8);
                cp16(sb + BL_OFF + off, sll + j * 8);
            }
            cp_commit();
            cp_wait0();
        }
        __syncthreads();

        for (int c = 0; c < NCHUNK; ++c) {
            const uint32_t st = (uint32_t)(c & 1);
            const bool pre = (c + 1 < NCHUNK);
            if (pre) {
                const int k0n = (c + 1) * 64;
                uint32_t nB = sb + (st ^ 1u) * STAGE;
                cp16(nB + aOff0, aG + k0n);
                cp16(nB + aOff1, aG + k0n + 8);
                const __half* shh =
                    Whi + (size_t)(n0 + bn) * KTOT + k0n + bseg0 * 8;
                const __half* sll =
                    Wlo + (size_t)(n0 + bn) * KTOT + k0n + bseg0 * 8;
#pragma unroll
                for (int j = 0; j < 4; ++j) {
                    uint32_t off =
                        bRow + (((uint32_t)((bseg0 + j) * 16)) ^ swb);
                    cp16(nB + BH_OFF + off, shh + j * 8);
                    cp16(nB + BL_OFF + off, sll + j * 8);
                }
                cp_commit();
            }

            // ---- compute on stage st
            {
                const uint32_t aB = sb + st * STAGE;
                const uint32_t bBh = aB + BH_OFF;
                const uint32_t bBl = aB + BL_OFF;
#pragma unroll
                for (int kf = 0; kf < 4; ++kf) {
                    const uint32_t cA = (((uint32_t)(kf * 32)) + klA) ^ swl;
                    const uint32_t cB = (((uint32_t)(kf * 32)) + klB) ^ swl;
                    unsigned ah0[4], ah1[4];
                    ldsm4(ah0, aB + rowA0 + cA);
                    ldsm4(ah1, aB + rowA1 + cA);
#pragma unroll
                    for (int nfp = 0; nfp < 2; ++nfp) {
                        unsigned bh[4], bl[4];
                        const uint32_t rB = nfp ? rowB1 : rowB0;
                        ldsm4(bh, bBh + rB + cB);
                        ldsm4(bl, bBl + rB + cB);
                        const int nf = 2 * nfp;
                        mma_f16(acc[0][nf], ah0, bh + 0);
                        mma_f16(acc[0][nf], ah0, bl + 0);
                        mma_f16(acc[1][nf], ah1, bh + 0);
                        mma_f16(acc[1][nf], ah1, bl + 0);
                        mma_f16(acc[0][nf + 1], ah0, bh + 2);
                        mma_f16(acc[0][nf + 1], ah0, bl + 2);
                        mma_f16(acc[1][nf + 1], ah1, bh + 2);
                        mma_f16(acc[1][nf + 1], ah1, bl + 2);
                    }
                }
            }

            if (pre) cp_wait0();
            __syncthreads();
        }

        // ---- epilogue: fold tanh(+bias)*avec into per-row score regs
#pragma unroll
        for (int nf = 0; nf < 4; ++nf) {
            int n = n0 + wn * 32 + nf * 8 + 2 * q;
            float bi0 = bias[n], bi1 = bias[n + 1];
            float a0 = avec[n], a1 = avec[n + 1];
#pragma unroll
            for (int mf = 0; mf < 2; ++mf) {
                sc[mf * 2 + 0] += tanhf(acc[mf][nf][0] + bi0) * a0 +
                                  tanhf(acc[mf][nf][1] + bi1) * a1;
                sc[mf * 2 + 1] += tanhf(acc[mf][nf][2] + bi0) * a0 +
                                  tanhf(acc[mf][nf][3] + bi1) * a1;
            }
        }
    }

    // reduce over q lanes (same row, different n columns)
#pragma unroll
    for (int j = 0; j < 4; ++j) {
        sc[j] += __shfl_xor_sync(0xFFFFFFFFu, sc[j], 1);
        sc[j] += __shfl_xor_sync(0xFFFFFFFFu, sc[j], 2);
    }
    if (q == 0) {
#pragma unroll
        for (int mf = 0; mf < 2; ++mf)
#pragma unroll
            for (int hb = 0; hb < 2; ++hb)
                atomicAdd(&ssc[wm * 32 + mf * 16 + hb * 8 + g],
                          sc[mf * 2 + hb]);
    }
    __syncthreads();
    if (tid < 64) {
        float v = ssc[tid];
        float* dst = &g_scores[b * S_ + s0 + tid];
        if (ADD)
            *dst += v;
        else
            *dst = v;
    }
}

// ---------------- kernel 5: combined softmax -> gamma ----------------------
__global__ void softmax_kernel(float* __restrict__ gamma_out) {
    __shared__ float red[256];
    int b = blockIdx.x, tid = threadIdx.x;        // 256 threads
    float v[8];
    float m = -1e30f;
#pragma unroll
    for (int i = 0; i < 8; ++i) {
        v[i] = g_scores[b * S_ + tid + i * 256];
        m = fmaxf(m, v[i]);
    }
    red[tid] = m;
    __syncthreads();
    for (int o = 128; o > 0; o >>= 1) {
        if (tid < o) red[tid] = fmaxf(red[tid], red[tid + o]);
        __syncthreads();
    }
    float M = red[0];
    __syncthreads();
    float s = 0.f;
#pragma unroll
    for (int i = 0; i < 8; ++i) {
        v[i] = expf(v[i] - M);
        s += v[i];
    }
    red[tid] = s;
    __syncthreads();
    for (int o = 128; o > 0; o >>= 1) {
        if (tid < o) red[tid] += red[tid + o];
        __syncthreads();
    }
    float inv = 1.0f / red[0];
#pragma unroll
    for (int i = 0; i < 8; ++i) gamma_out[b * S_ + tid + i * 256] = v[i] * inv;
}

// ---------------- kernel 6: weighted context --------------------------------
__global__ void weighted_kernel(const float* __restrict__ ctx,
                                const float* __restrict__ gamma) {
    int scn = blockIdx.x, b = blockIdx.y, tid = threadIdx.x;  // 128 threads
    const float4* C4 = (const float4*)(ctx + (size_t)b * S_ * H_);
    const float* gp = gamma + b * S_ + scn * 256;
    float4 acc = {0.f, 0.f, 0.f, 0.f};
    int base = (scn * 256) * 128 + tid;
#pragma unroll 4
    for (int s = 0; s < 256; ++s) {
        float gv = gp[s];
        float4 v = C4[base + s * 128];
        acc.x += gv * v.x;
        acc.y += gv * v.y;
        acc.z += gv * v.z;
        acc.w += gv * v.w;
    }
    ((float4*)g_wcpart)[(scn * B_ + b) * 128 + tid] = acc;
}

// ---------------- kernel 7: h_tilde -----------------------------------------
__global__ void out_kernel(const float* __restrict__ input,
                           const float* __restrict__ W_out,
                           float* __restrict__ out) {
    __shared__ float x[2 * H_];
    int b = blockIdx.x, tid = threadIdx.x;        // 512 threads
    float w = 0.f;
#pragma unroll
    for (int p = 0; p < 8; ++p) w += g_wcpart[(p * B_ + b) * H_ + tid];
    x[tid] = w;
    x[H_ + tid] = input[b * H_ + tid];
    __syncthreads();
    float acc = 0.f;
#pragma unroll 8
    for (int j = 0; j < 2 * H_; ++j) acc += x[j] * W_out[j * H_ + tid];
    out[b * H_ + tid] = tanhf(acc);
}

// ---------------- launch ----------------------------------------------------
extern "C" void kernel_launch(void* const* d_in, const int* in_sizes, int n_in,
                              void* d_out, int out_size) {
    const float* input   = (const float*)d_in[0];
    const float* context = (const float*)d_in[1];
    const float* input_z = (const float*)d_in[2];
    const float* W_enc   = (const float*)d_in[3];
    const float* b_enc   = (const float*)d_in[4];
    const float* W_a     = (const float*)d_in[5];
    const float* b_a     = (const float*)d_in[6];
    const float* W_b     = (const float*)d_in[7];
    const float* b_b     = (const float*)d_in[8];
    const float* W_z     = (const float*)d_in[9];
    const float* b_z     = (const float*)d_in[10];
    const float* W_out   = (const float*)d_in[11];

    float* h_tilde = (float*)d_out;               // [B,H] first
    float* gamma   = (float*)d_out + B_ * H_;     // [B,S] second

    const int SMEM_SC = 2 * 40960;                // 80KB (two 40KB stages)
    cudaFuncSetAttribute(score_mma_kernel<H_, 0>,
                         cudaFuncAttributeMaxDynamicSharedMemorySize, SMEM_SC);
    cudaFuncSetAttribute(score_mma_kernel<F_, 1>,
                         cudaFuncAttributeMaxDynamicSharedMemorySize, SMEM_SC);

    conv16_kernel<<<(B_ * S_ * H_) / 2048, 256>>>(context, 0);
    conv16_kernel<<<(B_ * S_ * F_) / 2048, 256>>>(input_z, 1);
    prep_kernel<<<1024, 256>>>(W_enc, W_z);
    proj_in_kernel<<<B_, 256>>>(input, W_a, b_a, W_b, b_b);
    score_mma_kernel<H_, 0><<<B_ * 32, 256, SMEM_SC>>>(b_enc);
    score_mma_kernel<F_, 1><<<B_ * 32, 256, SMEM_SC>>>(b_z);
    softmax_kernel<<<B_, 256>>>(gamma);
    weighted_kernel<<<dim3(8, B_), 128>>>(context, gamma);
    out_kernel<<<B_, 512>>>(input, W_out, h_tilde);
}